// round 16
// baseline (speedup 1.0000x reference)
#include <cuda_runtime.h>

#define Lf 512
#define Bf 4096
#define Tt 25
#define NP 13      // i-pairs (2p, 2p+1); slot p=12 hi half = pad (i=25)
#define GST 32     // g_score row stride (128B-aligned rows)
#define WPB 8      // warps per block (256 thr -> SMSP-balanced)

__device__ float g_score[(size_t)Lf * Bf * GST];
__device__ float g_logz[Bf];
__device__ float g_num[Bf];

typedef unsigned long long u64;

__device__ __forceinline__ u64 pack2(float lo, float hi) {
    u64 r; asm("mov.b64 %0,{%1,%2};" : "=l"(r) : "f"(lo), "f"(hi)); return r;
}
__device__ __forceinline__ void un2(u64 v, float& a, float& b) {
    asm("mov.b64 {%0,%1},%2;" : "=f"(a), "=f"(b) : "l"(v));
}
__device__ __forceinline__ u64 fma2(u64 a, u64 b, u64 c) {
    u64 d; asm("fma.rn.f32x2 %0,%1,%2,%3;" : "=l"(d) : "l"(a), "l"(b), "l"(c)); return d;
}
__device__ __forceinline__ u64 add2(u64 a, u64 b) {
    u64 d; asm("add.rn.f32x2 %0,%1,%2;" : "=l"(d) : "l"(a), "l"(b)); return d;
}
__device__ __forceinline__ unsigned ford(float f) {
    unsigned v = __float_as_uint(f);
    return (v & 0x80000000u) ? ~v : (v | 0x80000000u);
}

// ---------------------------------------------------------------------------
// One fused forward+Viterbi step for both chains (R8 math, bit-identical).
__device__ __forceinline__ void fwd_step(
    float* dA, float* dB,                        // write regions (this buffer)
    const ulonglong2* pA, const ulonglong2* pB,  // read regions  (same buffer)
    int sp4sh, const u64* Ep, const u64* Tp,
    float& aA, float& vA, float& aB, float& vB,
    float eA, float eB,
    float& lgA, float& lgB,
    bool act, float*& gspA, float*& gspB)
{
    // publish state of previous step in packed layout
    dA[sp4sh] = aA;  dA[sp4sh + 2] = vA;
    dB[sp4sh] = aB;  dB[sp4sh + 2] = vB;
    __syncwarp();

    u64 rAe = 0ull, rAo = 0ull, rBe = 0ull, rBo = 0ull;
    float mA0 = -1e30f, mA1 = -1e30f, mA2 = -1e30f, mA3 = -1e30f;
    float mB0 = -1e30f, mB1 = -1e30f, mB2 = -1e30f, mB3 = -1e30f;
    float a0A = 0.f, a0B = 0.f;
#pragma unroll
    for (int p = 0; p < NP; p++) {
        ulonglong2 sA2 = pA[p];     // {a-pair, v-pair} broadcast LDS.128
        ulonglong2 sB2 = pB[p];
        float sx, sy;
        if (p == 0) {
            float hx, hy;
            un2(sA2.x, a0A, hx);
            un2(sB2.x, a0B, hy);
        }
        if (p & 1) {
            rAo = fma2(sA2.x, Ep[p], rAo);
            rBo = fma2(sB2.x, Ep[p], rBo);
            un2(add2(sA2.y, Tp[p]), sx, sy);
            mA2 = fmaxf(mA2, sx); mA3 = fmaxf(mA3, sy);
            un2(add2(sB2.y, Tp[p]), sx, sy);
            mB2 = fmaxf(mB2, sx); mB3 = fmaxf(mB3, sy);
        } else {
            rAe = fma2(sA2.x, Ep[p], rAe);
            rBe = fma2(sB2.x, Ep[p], rBe);
            un2(add2(sA2.y, Tp[p]), sx, sy);
            mA0 = fmaxf(mA0, sx); mA1 = fmaxf(mA1, sy);
            un2(add2(sB2.y, Tp[p]), sx, sy);
            mB0 = fmaxf(mB0, sx); mB1 = fmaxf(mB1, sy);
        }
    }
    const float laA = __logf(a0A);
    const float laB = __logf(a0B);
    lgA += laA; lgB += laB;

    float rx, ry;
    un2(add2(rAe, rAo), rx, ry);
    float uA = (rx + ry) * __expf(eA - laA);
    un2(add2(rBe, rBo), rx, ry);
    float uB = (rx + ry) * __expf(eB - laB);
    float svA = fmaxf(fmaxf(mA0, mA1), fmaxf(mA2, mA3)) + eA;  // exact (monotone)
    float svB = fmaxf(fmaxf(mB0, mB1), fmaxf(mB2, mB3)) + eB;

    aA = act ? uA : 0.f;   vA = act ? svA : -1e30f;
    aB = act ? uB : 0.f;   vB = act ? svB : -1e30f;
    if (act) { *gspA = svA; *gspB = svB; }
    gspA += (size_t)Bf * GST; gspB += (size_t)Bf * GST;
}

// One gold-path numerator step (executed by all lanes, branch-free; only
// lanes 0/1 store at the end). Exactly reference order: (acc + trans) + em.
__device__ __forceinline__ void num_step(
    int l, int nb, const float* em, const float* trans, const int* tags,
    int& prev, int& tg_cur, float& nacc)
{
    float tr = trans[prev * Tt + tg_cur];
    float e  = em[((size_t)l * Bf + nb) * Tt + tg_cur];
    nacc = (nacc + tr) + e;
    prev = tg_cur;
    if (l + 1 < Lf) tg_cur = tags[(size_t)(l + 1) * Bf + nb];
}

// Fused forward + Viterbi + gold-path numerator.
// 2 chains per warp, 256-thread blocks, grid 256 (R8 shape, reproducible best).
__global__ __launch_bounds__(32 * WPB, 2) void fwd_vit_kernel(
    const float* __restrict__ em, const float* __restrict__ trans,
    const float* __restrict__ start, const float* __restrict__ endt,
    const int* __restrict__ tags, float* __restrict__ out, int base)
{
    // [buf][warp][chain][slot 0..15][4 floats {a_lo,a_hi,v_lo,v_hi}]
    __shared__ __align__(16) float sst[2][WPB][2][16][4];

    const int lane = threadIdx.x & 31;
    const int wl   = threadIdx.x >> 5;
    const int w    = blockIdx.x * WPB + wl;            // 0..2047 (R8 mapping)
    const int bA   = w;
    const int bB   = w + Bf / 2;
    const bool act = lane < Tt;
    const int  j   = act ? lane : 0;
    const int  sp4sh = (lane >> 1) * 4 + (lane & 1);

    if (blockIdx.x == 0 && threadIdx.x == 0 && base > 0) out[0] = 0.f;

    float* dA0 = &sst[0][wl][0][0][0];
    float* dB0 = &sst[0][wl][1][0][0];
    float* dA1 = &sst[1][wl][0][0][0];
    float* dB1 = &sst[1][wl][1][0][0];
    const ulonglong2* pA0 = (const ulonglong2*)dA0;
    const ulonglong2* pB0 = (const ulonglong2*)dB0;
    const ulonglong2* pA1 = (const ulonglong2*)dA1;
    const ulonglong2* pB1 = (const ulonglong2*)dB1;

    // loop-invariant tables
    u64 Ep[NP], Tp[NP];
#pragma unroll
    for (int p = 0; p < NP; p++) {
        const int i0 = 2 * p, i1 = 2 * p + 1;
        float t0 = trans[i0 * Tt + j];
        float t1 = (i1 < Tt) ? trans[i1 * Tt + j] : -1e30f;
        Tp[p] = pack2(t0, t1);
        Ep[p] = pack2(__expf(t0), (i1 < Tt) ? __expf(t1) : 0.f);
    }

    // ---- l = 0 state + emission pipeline ----
    const size_t emstep = (size_t)Bf * Tt;
    const float* empA = em + (size_t)bA * Tt + j;
    const float* empB = em + (size_t)bB * Tt + j;
    float e0A = *empA, e0B = *empB;            // em[0]
    empA += emstep; empB += emstep;
    float eA_cur = *empA, eB_cur = *empB;      // em[1]
    empA += emstep; empB += emstep;
    float eA_nxt = *empA, eB_nxt = *empB;      // em[2]
    empA += emstep; empB += emstep;            // -> em[3]

    const float stj = start[j];
    float s0A = stj + e0A, s0B = stj + e0B;
    float aA = act ? __expf(s0A) : 0.f;
    float vA = act ? s0A : -1e30f;
    float aB = act ? __expf(s0B) : 0.f;
    float vB = act ? s0B : -1e30f;

    float* gspA = &g_score[(size_t)bA * GST + j];
    float* gspB = &g_score[(size_t)bB * GST + j];
    if (act) { *gspA = s0A; *gspB = s0B; }
    gspA += (size_t)Bf * GST; gspB += (size_t)Bf * GST;

    float lgA = 0.f, lgB = 0.f;

    // ---- numerator state (lane 0 -> chain bA, lane 1 -> chain bB; other
    //      lanes duplicate lane 0's work to stay branch-free) ----
    const int nb = (lane == 1) ? bB : bA;
    int tg_cur = tags[nb];                               // tags[0]
    float nacc = start[tg_cur] + em[(size_t)nb * Tt + tg_cur];
    int prev = tg_cur;
    tg_cur = tags[(size_t)Bf + nb];                      // tags[1]

    // ---- main loop: 511 steps, unrolled x2 over the double buffer ----
    for (int l = 1; l + 1 < Lf; l += 2) {
        fwd_step(dA0, dB0, pA0, pB0, sp4sh, Ep, Tp, aA, vA, aB, vB,
                 eA_cur, eB_cur, lgA, lgB, act, gspA, gspB);
        num_step(l, nb, em, trans, tags, prev, tg_cur, nacc);
        eA_cur = eA_nxt; eB_cur = eB_nxt;
        if (l + 2 < Lf) {
            eA_nxt = *empA; empA += emstep;
            eB_nxt = *empB; empB += emstep;
        }
        fwd_step(dA1, dB1, pA1, pB1, sp4sh, Ep, Tp, aA, vA, aB, vB,
                 eA_cur, eB_cur, lgA, lgB, act, gspA, gspB);
        num_step(l + 1, nb, em, trans, tags, prev, tg_cur, nacc);
        eA_cur = eA_nxt; eB_cur = eB_nxt;
        if (l + 3 < Lf) {
            eA_nxt = *empA; empA += emstep;
            eB_nxt = *empB; empB += emstep;
        }
    }
    fwd_step(dA0, dB0, pA0, pB0, sp4sh, Ep, Tp, aA, vA, aB, vB,
             eA_cur, eB_cur, lgA, lgB, act, gspA, gspB);   // l = 511
    num_step(Lf - 1, nb, em, trans, tags, prev, tg_cur, nacc);

    // numerator: + end_transitions[last_tag]; store (lanes 0/1 only)
    nacc += endt[prev];
    if (lane < 2) g_num[nb] = nacc;

    // logz = lg + log( sum_i a_final[i] * exp(end[i]) )
    float ee = __expf(endt[j]);
    float dA = act ? aA * ee : 0.f;
    float dB = act ? aB * ee : 0.f;
#pragma unroll
    for (int off = 16; off; off >>= 1) {
        dA += __shfl_xor_sync(0xffffffffu, dA, off);
        dB += __shfl_xor_sync(0xffffffffu, dB, off);
    }
    if (lane == 0) {
        g_logz[bA] = lgA + __logf(dA);
        g_logz[bB] = lgB + __logf(dB);
    }
}

// ---------------------------------------------------------------------------
__device__ __forceinline__ void bt_group(
    const float* __restrict__ em, const float* st, float* out, int base,
    int b, int lane, bool alive, int lbase, int& jn,
    float (&cs)[8], float (&ce)[8], float (&ns)[8], float (&ne)[8], bool load_next)
{
    if (load_next) {
#pragma unroll
        for (int k = 0; k < 8; k++) {
            int l = lbase - 8 - k;
            bool ok = alive && (l >= 0);
            ns[k] = ok ? g_score[((size_t)l * Bf + b) * GST + lane] : 0.f;
            ne[k] = ok ? em[((size_t)(l + 1) * Bf + b) * Tt + lane] : 0.f;
        }
    }
#pragma unroll
    for (int k = 0; k < 8; k++) {
        int l = lbase - k;
        float ej = __shfl_sync(0xffffffffu, ce[k], jn);
        float tt = alive ? (cs[k] + st[lane * Tt + jn]) + ej : -3e38f;
        unsigned uu = ford(tt);
        unsigned mx = __reduce_max_sync(0xffffffffu, uu);
        int j2 = __ffs(__ballot_sync(0xffffffffu, uu == mx)) - 1;
        if (l >= 0) {
            jn = j2;
            if (lane == 0) out[base + (size_t)l * Bf + b] = (float)jn;
        }
    }
}

__global__ __launch_bounds__(256) void backtrack_kernel(
    const float* __restrict__ em, const float* __restrict__ trans,
    const float* __restrict__ endt, float* __restrict__ out, int base)
{
    __shared__ float st[Tt * Tt];
    __shared__ float cpart[8];
    const int tid = threadIdx.x;
    for (int i = tid; i < Tt * Tt; i += 256) st[i] = trans[i];
    __syncthreads();

    const int b    = (blockIdx.x * 256 + tid) >> 5;
    const int lane = tid & 31;
    const bool alive = lane < Tt;

    float sc = alive ? g_score[((size_t)(Lf - 1) * Bf + b) * GST + lane] : -3e38f;
    float t  = alive ? sc + endt[lane] : -3e38f;
    unsigned u  = ford(t);
    unsigned um = __reduce_max_sync(0xffffffffu, u);
    int jn = __ffs(__ballot_sync(0xffffffffu, u == um)) - 1;
    if (lane == 0) out[base + (size_t)(Lf - 1) * Bf + b] = (float)jn;

    float sA[8], eA[8], sB[8], eB[8];
#pragma unroll
    for (int k = 0; k < 8; k++) {
        int l = Lf - 2 - k;
        sA[k] = alive ? g_score[((size_t)l * Bf + b) * GST + lane] : 0.f;
        eA[k] = alive ? em[((size_t)(l + 1) * Bf + b) * Tt + lane] : 0.f;
    }
    for (int g = 0; g < 64; g += 2) {
        bt_group(em, st, out, base, b, lane, alive, Lf - 2 - 8 * g, jn,
                 sA, eA, sB, eB, true);
        bt_group(em, st, out, base, b, lane, alive, Lf - 2 - 8 * (g + 1), jn,
                 sB, eB, sA, eA, g + 1 < 63);
    }

    float c = 0.f;
    if (lane == 0 && base > 0) c = (g_logz[b] - g_num[b]) * (1.0f / Bf);
    if (lane == 0) cpart[tid >> 5] = c;
    __syncthreads();
    if (tid == 0 && base > 0) {
        float sum = 0.f;
#pragma unroll
        for (int w = 0; w < 8; w++) sum += cpart[w];
        atomicAdd(out, sum);
    }
}

// ---------------------------------------------------------------------------
extern "C" void kernel_launch(void* const* d_in, const int* in_sizes, int n_in,
                              void* d_out, int out_size) {
    const float* em    = (const float*)d_in[0];
    const int*   tags  = (const int*)d_in[1];
    const float* trans = (const float*)d_in[2];
    const float* start = (const float*)d_in[3];
    const float* endt  = (const float*)d_in[4];
    float* out = (float*)d_out;

    int base = out_size - Lf * Bf;
    if (base < 0) base = 0;

    fwd_vit_kernel<<<Bf / (2 * WPB), 32 * WPB>>>(em, trans, start, endt,
                                                 tags, out, base);
    backtrack_kernel<<<(Bf * 32) / 256, 256>>>(em, trans, endt, out, base);
}

// round 17
// speedup vs baseline: 1.3793x; 1.3793x over previous
#include <cuda_runtime.h>

#define Lf 512
#define Bf 4096
#define Tt 25
#define NP 13      // i-pairs (2p, 2p+1); slot p=12 hi half = pad (i=25)
#define GST 32     // g_score row stride (128B-aligned rows)
#define WPB 8      // warps per block (256 thr -> SMSP-balanced)

__device__ float g_score[(size_t)Lf * Bf * GST];
__device__ float g_logz[Bf];
__device__ float g_num[Bf];

typedef unsigned long long u64;

__device__ __forceinline__ u64 pack2(float lo, float hi) {
    u64 r; asm("mov.b64 %0,{%1,%2};" : "=l"(r) : "f"(lo), "f"(hi)); return r;
}
__device__ __forceinline__ void un2(u64 v, float& a, float& b) {
    asm("mov.b64 {%0,%1},%2;" : "=f"(a), "=f"(b) : "l"(v));
}
__device__ __forceinline__ u64 fma2(u64 a, u64 b, u64 c) {
    u64 d; asm("fma.rn.f32x2 %0,%1,%2,%3;" : "=l"(d) : "l"(a), "l"(b), "l"(c)); return d;
}
__device__ __forceinline__ u64 add2(u64 a, u64 b) {
    u64 d; asm("add.rn.f32x2 %0,%1,%2;" : "=l"(d) : "l"(a), "l"(b)); return d;
}
__device__ __forceinline__ unsigned ford(float f) {
    unsigned v = __float_as_uint(f);
    return (v & 0x80000000u) ? ~v : (v | 0x80000000u);
}

// ---------------------------------------------------------------------------
__global__ void init_kernel(float* out, int base) {
    int i = blockIdx.x * blockDim.x + threadIdx.x;
    if (i < Bf) g_num[i] = 0.f;
    if (i == 0 && base > 0) out[0] = 0.f;
}

// ---------------------------------------------------------------------------
// Fused forward + Viterbi: 2 chains per warp. State kept in smem in packed
// i-pair layout {a2p, a2p+1, v2p, v2p+1} so the consumer LDS.128 feeds
// fma.rn.f32x2 / add.rn.f32x2 directly (no repacking MOVs).
__global__ __launch_bounds__(256, 2) void fwd_vit_kernel(
    const float* __restrict__ em, const float* __restrict__ trans,
    const float* __restrict__ start, const float* __restrict__ endt)
{
    // [buf][warp][chain][pair][4 floats: a_lo, a_hi, v_lo, v_hi]
    __shared__ __align__(16) float sst[2][WPB][2][NP][4];

    const int lane = threadIdx.x & 31;
    const int wl   = threadIdx.x >> 5;
    const int w    = blockIdx.x * WPB + wl;            // 0..2047
    const int bA   = w;
    const int bB   = w + Bf / 2;
    const bool act = lane < Tt;
    const int  j   = act ? lane : 0;
    const int  sp  = lane >> 1;                        // state slot
    const int  sh  = lane & 1;                         // half within pair
    const bool wr  = lane < 26;                        // state writers (25 = pad)

    // loop-invariant tables
    u64 Ep[NP], Tp[NP];
#pragma unroll
    for (int p = 0; p < NP; p++) {
        const int i0 = 2 * p, i1 = 2 * p + 1;
        float t0 = trans[i0 * Tt + j];
        float t1 = (i1 < Tt) ? trans[i1 * Tt + j] : -1e30f;
        Tp[p] = pack2(t0, t1);
        Ep[p] = pack2(__expf(t0), (i1 < Tt) ? __expf(t1) : 0.f);
    }

    // ---- l = 0 ----
    const float* empA = em + (size_t)bA * Tt + j;
    const float* empB = em + (size_t)bB * Tt + j;
    const size_t emstep = (size_t)Bf * Tt;
    float eA = act ? *empA : 0.f;   empA += emstep;
    float eB = act ? *empB : 0.f;   empB += emstep;
    const float stj = start[j];
    float s0A = stj + eA, s0B = stj + eB;
    float vA = act ? s0A : -1e30f,  vB = act ? s0B : -1e30f;
    float aA = act ? __expf(s0A) : 0.f, aB = act ? __expf(s0B) : 0.f;

    float* gspA = &g_score[(size_t)bA * GST + j];
    float* gspB = &g_score[(size_t)bB * GST + j];
    const size_t gstep = (size_t)Bf * GST;
    if (act) { *gspA = s0A; *gspB = s0B; }
    gspA += gstep; gspB += gstep;

    float enA = act ? *empA : 0.f;  empA += emstep;
    float enB = act ? *empB : 0.f;  empB += emstep;

    float logaccA = 0.f, logaccB = 0.f;

    for (int l = 1; l < Lf; l++) {
        // publish state of step l-1 in packed layout
        const int bp = (l - 1) & 1;
        if (wr) {
            float* dA = &sst[bp][wl][0][sp][0];
            float* dB = &sst[bp][wl][1][sp][0];
            dA[sh] = aA;  dA[2 + sh] = vA;
            dB[sh] = aB;  dB[2 + sh] = vB;
        }
        __syncwarp();

        float e_A = enA, e_B = enB;
        if (l < Lf - 1) {
            enA = act ? *empA : 0.f; empA += emstep;
            enB = act ? *empB : 0.f; empB += emstep;
        }

        const ulonglong2* pA = (const ulonglong2*)&sst[bp][wl][0][0][0];
        const ulonglong2* pB = (const ulonglong2*)&sst[bp][wl][1][0][0];

        u64 rA = 0ull, rB = 0ull;
        float mA0 = -1e30f, mA1 = -1e30f, mB0 = -1e30f, mB1 = -1e30f;
        float a0A = 0.f, a0B = 0.f;
#pragma unroll
        for (int p = 0; p < NP; p++) {
            ulonglong2 sA2 = pA[p];     // .x = a-pair, .y = v-pair (broadcast)
            ulonglong2 sB2 = pB[p];
            if (p == 0) {
                float hx, hy;
                un2(sA2.x, a0A, hx);
                un2(sB2.x, a0B, hy);
            }
            rA = fma2(sA2.x, Ep[p], rA);
            rB = fma2(sB2.x, Ep[p], rB);
            float sx, sy;
            un2(add2(sA2.y, Tp[p]), sx, sy);
            mA0 = fmaxf(mA0, sx); mA1 = fmaxf(mA1, sy);
            un2(add2(sB2.y, Tp[p]), sx, sy);
            mB0 = fmaxf(mB0, sx); mB1 = fmaxf(mB1, sy);
        }
        const float laA = __logf(a0A);
        const float laB = __logf(a0B);
        logaccA += laA; logaccB += laB;

        float rx, ry;
        un2(rA, rx, ry); float uA = (rx + ry) * __expf(e_A - laA);
        un2(rB, rx, ry); float uB = (rx + ry) * __expf(e_B - laB);
        float svA = fmaxf(mA0, mA1) + e_A;    // == max_i((v+T)+e) (monotone add)
        float svB = fmaxf(mB0, mB1) + e_B;

        aA = act ? uA : 0.f;   vA = act ? svA : -1e30f;
        aB = act ? uB : 0.f;   vB = act ? svB : -1e30f;
        if (act) { *gspA = svA; *gspB = svB; }
        gspA += gstep; gspB += gstep;
    }

    // logz = sum log(scale) + log( sum_i a_final[i] * exp(end[i]) )
    float ee = __expf(endt[j]);
    float dA = act ? aA * ee : 0.f;
    float dB = act ? aB * ee : 0.f;
#pragma unroll
    for (int off = 16; off; off >>= 1) {
        dA += __shfl_xor_sync(0xffffffffu, dA, off);
        dB += __shfl_xor_sync(0xffffffffu, dB, off);
    }
    if (lane == 0) {
        g_logz[bA] = logaccA + __logf(dA);
        g_logz[bB] = logaccB + __logf(dB);
    }
}

// ---------------------------------------------------------------------------
__global__ void numer_kernel(const float* __restrict__ em, const int* __restrict__ tags,
                             const float* __restrict__ trans, const float* __restrict__ start,
                             const float* __restrict__ endt)
{
    int idx = blockIdx.x * blockDim.x + threadIdx.x;
    if (idx >= Bf * 32) return;
    int b  = idx & (Bf - 1);
    int c  = idx >> 12;
    int l0 = c * 16;
    float acc = 0.f;
    int prev = 0;
    if (c > 0) prev = tags[(size_t)(l0 - 1) * Bf + b];
#pragma unroll
    for (int dl = 0; dl < 16; dl++) {
        int l  = l0 + dl;
        int tg = tags[(size_t)l * Bf + b];
        acc += em[((size_t)l * Bf + b) * Tt + tg];
        if (l == 0) acc += start[tg];
        else        acc += trans[prev * Tt + tg];
        prev = tg;
    }
    if (l0 + 16 == Lf) acc += endt[prev];
    atomicAdd(&g_num[b], acc);
}

// ---------------------------------------------------------------------------
__device__ __forceinline__ void bt_group(
    const float* __restrict__ em, const float* st, float* out, int base,
    int b, int lane, bool alive, int lbase, int& jn,
    float (&cs)[8], float (&ce)[8], float (&ns)[8], float (&ne)[8], bool load_next)
{
    if (load_next) {
#pragma unroll
        for (int k = 0; k < 8; k++) {
            int l = lbase - 8 - k;
            bool ok = alive && (l >= 0);
            ns[k] = ok ? g_score[((size_t)l * Bf + b) * GST + lane] : 0.f;
            ne[k] = ok ? em[((size_t)(l + 1) * Bf + b) * Tt + lane] : 0.f;
        }
    }
#pragma unroll
    for (int k = 0; k < 8; k++) {
        int l = lbase - k;
        float ej = __shfl_sync(0xffffffffu, ce[k], jn);
        float tt = alive ? (cs[k] + st[lane * Tt + jn]) + ej : -3e38f;
        unsigned uu = ford(tt);
        unsigned mx = __reduce_max_sync(0xffffffffu, uu);
        int j2 = __ffs(__ballot_sync(0xffffffffu, uu == mx)) - 1;
        if (l >= 0) {
            jn = j2;
            if (lane == 0) out[base + (size_t)l * Bf + b] = (float)jn;
        }
    }
}

__global__ __launch_bounds__(256) void backtrack_kernel(
    const float* __restrict__ em, const float* __restrict__ trans,
    const float* __restrict__ endt, float* __restrict__ out, int base)
{
    __shared__ float st[Tt * Tt];
    __shared__ float cpart[8];
    const int tid = threadIdx.x;
    for (int i = tid; i < Tt * Tt; i += 256) st[i] = trans[i];
    __syncthreads();

    const int b    = (blockIdx.x * 256 + tid) >> 5;
    const int lane = tid & 31;
    const bool alive = lane < Tt;

    float sc = alive ? g_score[((size_t)(Lf - 1) * Bf + b) * GST + lane] : -3e38f;
    float t  = alive ? sc + endt[lane] : -3e38f;
    unsigned u  = ford(t);
    unsigned um = __reduce_max_sync(0xffffffffu, u);
    int jn = __ffs(__ballot_sync(0xffffffffu, u == um)) - 1;
    if (lane == 0) out[base + (size_t)(Lf - 1) * Bf + b] = (float)jn;

    float sA[8], eA[8], sB[8], eB[8];
#pragma unroll
    for (int k = 0; k < 8; k++) {
        int l = Lf - 2 - k;
        sA[k] = alive ? g_score[((size_t)l * Bf + b) * GST + lane] : 0.f;
        eA[k] = alive ? em[((size_t)(l + 1) * Bf + b) * Tt + lane] : 0.f;
    }
    for (int g = 0; g < 64; g += 2) {
        bt_group(em, st, out, base, b, lane, alive, Lf - 2 - 8 * g, jn,
                 sA, eA, sB, eB, true);
        bt_group(em, st, out, base, b, lane, alive, Lf - 2 - 8 * (g + 1), jn,
                 sB, eB, sA, eA, g + 1 < 63);
    }

    float c = 0.f;
    if (lane == 0 && base > 0) c = (g_logz[b] - g_num[b]) * (1.0f / Bf);
    if (lane == 0) cpart[tid >> 5] = c;
    __syncthreads();
    if (tid == 0 && base > 0) {
        float sum = 0.f;
#pragma unroll
        for (int w = 0; w < 8; w++) sum += cpart[w];
        atomicAdd(out, sum);
    }
}

// ---------------------------------------------------------------------------
extern "C" void kernel_launch(void* const* d_in, const int* in_sizes, int n_in,
                              void* d_out, int out_size) {
    const float* em    = (const float*)d_in[0];
    const int*   tags  = (const int*)d_in[1];
    const float* trans = (const float*)d_in[2];
    const float* start = (const float*)d_in[3];
    const float* endt  = (const float*)d_in[4];
    float* out = (float*)d_out;

    int base = out_size - Lf * Bf;
    if (base < 0) base = 0;

    init_kernel<<<16, 256>>>(out, base);
    fwd_vit_kernel<<<Bf / (2 * WPB), 32 * WPB>>>(em, trans, start, endt);
    numer_kernel<<<(Bf * 32) / 256, 256>>>(em, tags, trans, start, endt);
    backtrack_kernel<<<(Bf * 32) / 256, 256>>>(em, trans, endt, out, base);
}